// round 16
// baseline (speedup 1.0000x reference)
#include <cuda_runtime.h>
#include <cuda_fp16.h>
#include <cstdint>

#define N_NODES 100000
#define N_EDGES 1600000
#define IN_F    128
#define OUT_F   32

typedef unsigned long long u64;

// Scratch (__device__ globals; no allocation anywhere in this file).
__device__ int    g_deg[N_NODES];              // indeg (memset to 0 each call)
__device__ u64    g_W2 [(IN_F / 2) * OUT_F];   // packed W pairs: [k2][f]
__device__ __align__(4) __half g_hs[N_NODES * OUT_F];  // fp16 message h*dis
__device__ __align__(16) int g_ptr [N_NODES + 4];
__device__ __align__(16) int g_fill[N_NODES + 4];
__device__ __align__(16) int g_csrc[N_EDGES];  // CSR: src ids bucketed by dst

#define SCAN_NB ((N_NODES + 1023) / 1024)      // 98
__device__ u64    g_stat[SCAN_NB];             // lookback state: (sum<<2)|flag

#define DEG_BLK (N_EDGES / 256)                // 6250 (exact)
#define LIN_BLK ((N_NODES + 63) / 64)          // 1563

// ---------------------------------------------------------------------------
// L1: grid-fused pre-pass: indeg count | W pack | lookback-state zero.
__global__ void k_pre(const int* __restrict__ ei, const float* __restrict__ W) {
    int bid = blockIdx.x, t = threadIdx.x;
    if (bid < DEG_BLK) {
        int e = bid * 256 + t;
        atomicAdd(&g_deg[ei[N_EDGES + e]], 1);
    } else if (bid < DEG_BLK + 8) {
        int i  = (bid - DEG_BLK) * 256 + t;
        int k2 = i >> 5, f = i & 31;
        float w0 = W[f * IN_F + 2 * k2];
        float w1 = W[f * IN_F + 2 * k2 + 1];
        g_W2[i] = ((u64)__float_as_uint(w1) << 32) | (u64)__float_as_uint(w0);
    } else {
        if (t < SCAN_NB) g_stat[t] = 0;
    }
}

// ---------------------------------------------------------------------------
// L2: single-pass exclusive scan of indeg (decoupled lookback) -> ptr, fill.
__device__ __forceinline__ void stat_pub(int bid, int val, unsigned flag) {
    atomicExch(&g_stat[bid], ((u64)(unsigned)val << 2) | (u64)flag);
}

__global__ __launch_bounds__(256) void k_scan() {
    __shared__ int ws[8], wexcl_s[8];
    __shared__ int s_btot, s_prefix;
    int t = threadIdx.x, lane = t & 31, wid = t >> 5, bid = blockIdx.x;
    int i0 = bid * 1024 + t * 4;

    int va[4];
    #pragma unroll
    for (int j = 0; j < 4; j++)
        va[j] = (i0 + j < N_NODES) ? g_deg[i0 + j] : 0;
    int s01 = va[0] + va[1], s012 = s01 + va[2], tsum = s012 + va[3];

    int inc = tsum;
    #pragma unroll
    for (int o = 1; o < 32; o <<= 1) {
        int n = __shfl_up_sync(0xffffffffu, inc, o);
        if (lane >= o) inc += n;
    }
    if (lane == 31) ws[wid] = inc;
    __syncthreads();
    if (wid == 0) {
        int wv = (lane < 8) ? ws[lane] : 0;
        int wi = wv;
        #pragma unroll
        for (int o = 1; o < 8; o <<= 1) {
            int n = __shfl_up_sync(0xffffffffu, wi, o);
            if (lane >= o) wi += n;
        }
        if (lane < 8) wexcl_s[lane] = wi - wv;
        if (lane == 7) s_btot = wi;
    }
    __syncthreads();

    if (t == 0) {
        int btot = s_btot, prefix = 0;
        if (bid == 0) {
            stat_pub(0, btot, 2u);
        } else {
            stat_pub(bid, btot, 1u);
            int i = bid - 1;
            while (true) {
                u64 s;
                do { s = *((volatile u64*)&g_stat[i]); } while ((s & 3ull) == 0ull);
                prefix += (int)(unsigned)(s >> 2);
                if ((s & 3ull) == 2ull) break;
                i--;
            }
            stat_pub(bid, prefix + btot, 2u);
        }
        s_prefix = prefix;
    }
    __syncthreads();

    int texcl = s_prefix + wexcl_s[wid] + (inc - tsum);
    int4 p = make_int4(texcl, texcl + va[0], texcl + s01, texcl + s012);
    if (i0 + 3 < N_NODES) {
        *(int4*)&g_ptr [i0] = p;
        *(int4*)&g_fill[i0] = p;
    } else {
        int pv[4] = {p.x, p.y, p.z, p.w};
        for (int j = 0; j < 4 && i0 + j < N_NODES; j++) {
            g_ptr[i0 + j] = pv[j]; g_fill[i0 + j] = pv[j];
        }
    }
    if (bid == 0 && t == 0) g_ptr[N_NODES] = N_EDGES;
}

// ---------------------------------------------------------------------------
// L3: linear (FFMA2, shared-staged) with the CSR-build phase hoisted BEFORE
// the FMA wall so its atomic latency overlaps compute.
#define NODES_PER_WARP 8
#define NODES_PER_BLK  64
#define FFMA2(acc, a, b) \
    asm("fma.rn.f32x2 %0, %1, %2, %0;" : "+l"(acc) : "l"(a), "l"(b))
#define CP_ASYNC16(saddr, gptr) \
    asm volatile("cp.async.cg.shared.global [%0], [%1], 16;" \
                 :: "r"(saddr), "l"(gptr) : "memory")

__global__ __launch_bounds__(256) void k_linear(const float* __restrict__ x,
                                                const int* __restrict__ ei) {
    __shared__ u64   sW2[IN_F / 2][OUT_F];
    __shared__ float sx[NODES_PER_BLK][IN_F];

    int tid = threadIdx.x;
    int node0 = blockIdx.x * NODES_PER_BLK;
    bool full = (node0 + NODES_PER_BLK <= N_NODES);

    const float4* xg = (const float4*)(x + (size_t)node0 * IN_F);
    float4* sx4 = (float4*)sx;
    if (full) {
        unsigned sbase;
        asm("{ .reg .u64 t; cvta.to.shared.u64 t, %1; cvt.u32.u64 %0, t; }"
            : "=r"(sbase) : "l"(sx4));
        #pragma unroll
        for (int i = 0; i < 8; i++) {
            int idx = tid + i * 256;
            CP_ASYNC16(sbase + idx * 16, xg + idx);
        }
        asm volatile("cp.async.commit_group;" ::: "memory");
    } else {
        #pragma unroll
        for (int i = 0; i < 8; i++) {
            int idx = tid + i * 256;
            sx4[idx] = (node0 + (idx >> 5) < N_NODES) ? xg[idx]
                                                      : make_float4(0.f, 0.f, 0.f, 0.f);
        }
    }

    {   // W pairs: coalesced u64 copy
        u64* sW = &sW2[0][0];
        #pragma unroll
        for (int i = 0; i < 8; i++)
            sW[tid + i * 256] = g_W2[tid + i * 256];
    }

    // --- CSR phase (independent of smem): overlaps staging + upcoming FMA ---
    #pragma unroll
    for (int i = 0; i < 4; i++) {
        int e = blockIdx.x * 1024 + i * 256 + tid;
        if (e < N_EDGES) {
            int dst = ei[N_EDGES + e];
            int pos = atomicAdd(&g_fill[dst], 1);
            g_csrc[pos] = ei[e];
        }
    }

    if (full) asm volatile("cp.async.wait_group 0;" ::: "memory");
    __syncthreads();

    int warp = tid >> 5;
    int f    = tid & 31;
    int nb   = warp * NODES_PER_WARP;

    u64 acc2[NODES_PER_WARP];
    #pragma unroll
    for (int n = 0; n < NODES_PER_WARP; n++) acc2[n] = 0ull;

    #pragma unroll 8
    for (int k4 = 0; k4 < IN_F / 4; k4++) {
        u64 wa = sW2[2 * k4 + 0][f];
        u64 wb = sW2[2 * k4 + 1][f];
        #pragma unroll
        for (int n = 0; n < NODES_PER_WARP; n++) {
            ulonglong2 xv = *(const ulonglong2*)&sx[nb + n][k4 * 4];
            FFMA2(acc2[n], xv.x, wa);
            FFMA2(acc2[n], xv.y, wb);
        }
    }

    #pragma unroll
    for (int n = 0; n < NODES_PER_WARP; n++) {
        int node = node0 + nb + n;
        if (node < N_NODES) {
            float lo = __uint_as_float((unsigned)(acc2[n] & 0xFFFFFFFFull));
            float hi = __uint_as_float((unsigned)(acc2[n] >> 32));
            float d  = rsqrtf((float)(g_deg[node] + 1));
            g_hs[node * OUT_F + f] = __float2half((lo + hi) * d);
        }
    }
}

// ---------------------------------------------------------------------------
// L4: aggregate + finalize. 2 nodes per warp (16-lane segment per node),
// half2 gathers (features 2fl,2fl+1), int4 index loads, fp32 accumulation.
__global__ __launch_bounds__(256) void k_aggregate(const float* __restrict__ b,
                                                   float* __restrict__ out) {
    int gtid = blockIdx.x * blockDim.x + threadIdx.x;
    int warp = gtid >> 5;
    int lane = gtid & 31;
    int seg  = lane >> 4;                 // 0/1: which node of the pair
    int fl   = lane & 15;                 // feature-pair index
    int node = warp * 2 + seg;            // 50000 warps * 2 = N_NODES exactly

    const __half2* hs2 = (const __half2*)g_hs;
    int rowb = node * (OUT_F / 2);

    float2 acc = __half22float2(hs2[rowb + fl]);      // self-loop term

    int j   = g_ptr[node];
    int end = g_ptr[node + 1];

    while (j < end && (j & 3)) {                      // align to int4
        float2 v = __half22float2(hs2[g_csrc[j] * (OUT_F / 2) + fl]);
        acc.x += v.x; acc.y += v.y;
        j++;
    }
    for (; j + 4 <= end; j += 4) {
        int4 s = *(const int4*)&g_csrc[j];            // 4 src ids, one LDG.128
        __half2 h0 = hs2[s.x * (OUT_F / 2) + fl];     // 4 gathers in flight
        __half2 h1 = hs2[s.y * (OUT_F / 2) + fl];
        __half2 h2 = hs2[s.z * (OUT_F / 2) + fl];
        __half2 h3 = hs2[s.w * (OUT_F / 2) + fl];
        float2 f0 = __half22float2(h0);
        float2 f1 = __half22float2(h1);
        float2 f2 = __half22float2(h2);
        float2 f3 = __half22float2(h3);
        acc.x += f0.x + f1.x + f2.x + f3.x;
        acc.y += f0.y + f1.y + f2.y + f3.y;
    }
    for (; j < end; j++) {
        float2 v = __half22float2(hs2[g_csrc[j] * (OUT_F / 2) + fl]);
        acc.x += v.x; acc.y += v.y;
    }

    float d = rsqrtf((float)(g_deg[node] + 1));
    float2 o;
    o.x = fmaf(acc.x, d, b[2 * fl + 0]);
    o.y = fmaf(acc.y, d, b[2 * fl + 1]);
    ((float2*)out)[rowb + fl] = o;                    // coalesced 128B per node pair
}

// ---------------------------------------------------------------------------
extern "C" void kernel_launch(void* const* d_in, const int* in_sizes, int n_in,
                              void* d_out, int out_size) {
    const float* x  = (const float*)d_in[0];
    const int*   ei = (const int*)d_in[1];     // int32 (harness downcasts int64)
    const float* W  = (const float*)d_in[2];
    const float* b  = (const float*)d_in[3];
    float*       out = (float*)d_out;

    (void)in_sizes; (void)n_in; (void)out_size;

    void* pdeg = nullptr;
    cudaGetSymbolAddress(&pdeg, g_deg);
    cudaMemsetAsync(pdeg, 0, N_NODES * sizeof(int), 0);

    k_pre      <<<DEG_BLK + 9, 256>>>(ei, W);
    k_scan     <<<SCAN_NB, 256>>>();
    k_linear   <<<LIN_BLK, 256>>>(x, ei);
    k_aggregate<<<(N_NODES / 2 * 32) / 256, 256>>>(b, out);   // 6250 blocks
}

// round 17
// speedup vs baseline: 1.1525x; 1.1525x over previous
#include <cuda_runtime.h>
#include <cuda_fp16.h>
#include <cstdint>

#define N_NODES 100000
#define N_EDGES 1600000
#define IN_F    128
#define OUT_F   32

typedef unsigned long long u64;

// Scratch (__device__ globals; no allocation anywhere in this file).
__device__ int    g_deg[N_NODES];              // indeg (memset to 0 each call)
__device__ u64    g_W2 [(IN_F / 2) * OUT_F];   // packed W pairs: [k2][f]
__device__ __align__(4) __half g_hs[N_NODES * OUT_F];  // fp16 message h*dis
__device__ __align__(16) int g_ptr [N_NODES + 4];
__device__ __align__(16) int g_fill[N_NODES + 4];
__device__ __align__(16) int g_csrc[N_EDGES];  // CSR: src ids bucketed by dst

#define SCAN_NB ((N_NODES + 1023) / 1024)      // 98
__device__ u64    g_stat[SCAN_NB];             // lookback state: (sum<<2)|flag

#define DEG_BLK (N_EDGES / 256)                // 6250 (exact)
#define LIN_BLK ((N_NODES + 63) / 64)          // 1563

// ---------------------------------------------------------------------------
// L1: grid-fused pre-pass: indeg count | W pack | lookback-state zero.
__global__ void k_pre(const int* __restrict__ ei, const float* __restrict__ W) {
    int bid = blockIdx.x, t = threadIdx.x;
    if (bid < DEG_BLK) {
        int e = bid * 256 + t;
        atomicAdd(&g_deg[ei[N_EDGES + e]], 1);
    } else if (bid < DEG_BLK + 8) {
        int i  = (bid - DEG_BLK) * 256 + t;
        int k2 = i >> 5, f = i & 31;
        float w0 = W[f * IN_F + 2 * k2];
        float w1 = W[f * IN_F + 2 * k2 + 1];
        g_W2[i] = ((u64)__float_as_uint(w1) << 32) | (u64)__float_as_uint(w0);
    } else {
        if (t < SCAN_NB) g_stat[t] = 0;
    }
}

// ---------------------------------------------------------------------------
// L2: single-pass exclusive scan of indeg (decoupled lookback) -> ptr, fill.
__device__ __forceinline__ void stat_pub(int bid, int val, unsigned flag) {
    atomicExch(&g_stat[bid], ((u64)(unsigned)val << 2) | (u64)flag);
}

__global__ __launch_bounds__(256) void k_scan() {
    __shared__ int ws[8], wexcl_s[8];
    __shared__ int s_btot, s_prefix;
    int t = threadIdx.x, lane = t & 31, wid = t >> 5, bid = blockIdx.x;
    int i0 = bid * 1024 + t * 4;

    int va[4];
    #pragma unroll
    for (int j = 0; j < 4; j++)
        va[j] = (i0 + j < N_NODES) ? g_deg[i0 + j] : 0;
    int s01 = va[0] + va[1], s012 = s01 + va[2], tsum = s012 + va[3];

    int inc = tsum;
    #pragma unroll
    for (int o = 1; o < 32; o <<= 1) {
        int n = __shfl_up_sync(0xffffffffu, inc, o);
        if (lane >= o) inc += n;
    }
    if (lane == 31) ws[wid] = inc;
    __syncthreads();
    if (wid == 0) {
        int wv = (lane < 8) ? ws[lane] : 0;
        int wi = wv;
        #pragma unroll
        for (int o = 1; o < 8; o <<= 1) {
            int n = __shfl_up_sync(0xffffffffu, wi, o);
            if (lane >= o) wi += n;
        }
        if (lane < 8) wexcl_s[lane] = wi - wv;
        if (lane == 7) s_btot = wi;
    }
    __syncthreads();

    if (t == 0) {
        int btot = s_btot, prefix = 0;
        if (bid == 0) {
            stat_pub(0, btot, 2u);
        } else {
            stat_pub(bid, btot, 1u);
            int i = bid - 1;
            while (true) {
                u64 s;
                do { s = *((volatile u64*)&g_stat[i]); } while ((s & 3ull) == 0ull);
                prefix += (int)(unsigned)(s >> 2);
                if ((s & 3ull) == 2ull) break;
                i--;
            }
            stat_pub(bid, prefix + btot, 2u);
        }
        s_prefix = prefix;
    }
    __syncthreads();

    int texcl = s_prefix + wexcl_s[wid] + (inc - tsum);
    int4 p = make_int4(texcl, texcl + va[0], texcl + s01, texcl + s012);
    if (i0 + 3 < N_NODES) {
        *(int4*)&g_ptr [i0] = p;
        *(int4*)&g_fill[i0] = p;
    } else {
        int pv[4] = {p.x, p.y, p.z, p.w};
        for (int j = 0; j < 4 && i0 + j < N_NODES; j++) {
            g_ptr[i0 + j] = pv[j]; g_fill[i0 + j] = pv[j];
        }
    }
    if (bid == 0 && t == 0) g_ptr[N_NODES] = N_EDGES;
}

// ---------------------------------------------------------------------------
// L3: linear (FFMA2, shared-staged) + CSR-build TAIL (after FMA — proven R15
// placement; hoisting it before the barrier serializes the ATOMG chain).
#define NODES_PER_WARP 8
#define NODES_PER_BLK  64
#define FFMA2(acc, a, b) \
    asm("fma.rn.f32x2 %0, %1, %2, %0;" : "+l"(acc) : "l"(a), "l"(b))
#define CP_ASYNC16(saddr, gptr) \
    asm volatile("cp.async.cg.shared.global [%0], [%1], 16;" \
                 :: "r"(saddr), "l"(gptr) : "memory")

__global__ __launch_bounds__(256) void k_linear(const float* __restrict__ x,
                                                const int* __restrict__ ei) {
    __shared__ u64   sW2[IN_F / 2][OUT_F];
    __shared__ float sx[NODES_PER_BLK][IN_F];

    int tid = threadIdx.x;
    int node0 = blockIdx.x * NODES_PER_BLK;
    bool full = (node0 + NODES_PER_BLK <= N_NODES);

    const float4* xg = (const float4*)(x + (size_t)node0 * IN_F);
    float4* sx4 = (float4*)sx;
    if (full) {
        unsigned sbase;
        asm("{ .reg .u64 t; cvta.to.shared.u64 t, %1; cvt.u32.u64 %0, t; }"
            : "=r"(sbase) : "l"(sx4));
        #pragma unroll
        for (int i = 0; i < 8; i++) {
            int idx = tid + i * 256;
            CP_ASYNC16(sbase + idx * 16, xg + idx);
        }
        asm volatile("cp.async.commit_group;" ::: "memory");
    } else {
        #pragma unroll
        for (int i = 0; i < 8; i++) {
            int idx = tid + i * 256;
            sx4[idx] = (node0 + (idx >> 5) < N_NODES) ? xg[idx]
                                                      : make_float4(0.f, 0.f, 0.f, 0.f);
        }
    }

    {   // W pairs: coalesced u64 copy
        u64* sW = &sW2[0][0];
        #pragma unroll
        for (int i = 0; i < 8; i++)
            sW[tid + i * 256] = g_W2[tid + i * 256];
    }

    if (full) asm volatile("cp.async.wait_group 0;" ::: "memory");
    __syncthreads();

    int warp = tid >> 5;
    int f    = tid & 31;
    int nb   = warp * NODES_PER_WARP;

    u64 acc2[NODES_PER_WARP];
    #pragma unroll
    for (int n = 0; n < NODES_PER_WARP; n++) acc2[n] = 0ull;

    #pragma unroll 8
    for (int k4 = 0; k4 < IN_F / 4; k4++) {
        u64 wa = sW2[2 * k4 + 0][f];
        u64 wb = sW2[2 * k4 + 1][f];
        #pragma unroll
        for (int n = 0; n < NODES_PER_WARP; n++) {
            ulonglong2 xv = *(const ulonglong2*)&sx[nb + n][k4 * 4];
            FFMA2(acc2[n], xv.x, wa);
            FFMA2(acc2[n], xv.y, wb);
        }
    }

    #pragma unroll
    for (int n = 0; n < NODES_PER_WARP; n++) {
        int node = node0 + nb + n;
        if (node < N_NODES) {
            float lo = __uint_as_float((unsigned)(acc2[n] & 0xFFFFFFFFull));
            float hi = __uint_as_float((unsigned)(acc2[n] >> 32));
            float d  = rsqrtf((float)(g_deg[node] + 1));
            g_hs[node * OUT_F + f] = __float2half((lo + hi) * d);
        }
    }

    // --- CSR tail: this block's 1024-edge chunk ---
    #pragma unroll
    for (int i = 0; i < 4; i++) {
        int e = blockIdx.x * 1024 + i * 256 + tid;
        if (e < N_EDGES) {
            int dst = ei[N_EDGES + e];
            int pos = atomicAdd(&g_fill[dst], 1);
            g_csrc[pos] = ei[e];
        }
    }
}

// ---------------------------------------------------------------------------
// L4: aggregate + finalize. 2 nodes per warp (16-lane segment per node),
// half2 gathers, int4 index loads, fp32 accumulation. (Measured 27.5µs.)
__global__ __launch_bounds__(256) void k_aggregate(const float* __restrict__ b,
                                                   float* __restrict__ out) {
    int gtid = blockIdx.x * blockDim.x + threadIdx.x;
    int warp = gtid >> 5;
    int lane = gtid & 31;
    int seg  = lane >> 4;                 // 0/1: which node of the pair
    int fl   = lane & 15;                 // feature-pair index
    int node = warp * 2 + seg;            // 50000 warps * 2 = N_NODES exactly

    const __half2* hs2 = (const __half2*)g_hs;
    int rowb = node * (OUT_F / 2);

    float2 acc = __half22float2(hs2[rowb + fl]);      // self-loop term

    int j   = g_ptr[node];
    int end = g_ptr[node + 1];

    while (j < end && (j & 3)) {                      // align to int4
        float2 v = __half22float2(hs2[g_csrc[j] * (OUT_F / 2) + fl]);
        acc.x += v.x; acc.y += v.y;
        j++;
    }
    for (; j + 4 <= end; j += 4) {
        int4 s = *(const int4*)&g_csrc[j];            // 4 src ids, one LDG.128
        __half2 h0 = hs2[s.x * (OUT_F / 2) + fl];     // 4 gathers in flight
        __half2 h1 = hs2[s.y * (OUT_F / 2) + fl];
        __half2 h2 = hs2[s.z * (OUT_F / 2) + fl];
        __half2 h3 = hs2[s.w * (OUT_F / 2) + fl];
        float2 f0 = __half22float2(h0);
        float2 f1 = __half22float2(h1);
        float2 f2 = __half22float2(h2);
        float2 f3 = __half22float2(h3);
        acc.x += f0.x + f1.x + f2.x + f3.x;
        acc.y += f0.y + f1.y + f2.y + f3.y;
    }
    for (; j < end; j++) {
        float2 v = __half22float2(hs2[g_csrc[j] * (OUT_F / 2) + fl]);
        acc.x += v.x; acc.y += v.y;
    }

    float d = rsqrtf((float)(g_deg[node] + 1));
    float2 o;
    o.x = fmaf(acc.x, d, b[2 * fl + 0]);
    o.y = fmaf(acc.y, d, b[2 * fl + 1]);
    ((float2*)out)[rowb + fl] = o;                    // coalesced
}

// ---------------------------------------------------------------------------
extern "C" void kernel_launch(void* const* d_in, const int* in_sizes, int n_in,
                              void* d_out, int out_size) {
    const float* x  = (const float*)d_in[0];
    const int*   ei = (const int*)d_in[1];     // int32 (harness downcasts int64)
    const float* W  = (const float*)d_in[2];
    const float* b  = (const float*)d_in[3];
    float*       out = (float*)d_out;

    (void)in_sizes; (void)n_in; (void)out_size;

    void* pdeg = nullptr;
    cudaGetSymbolAddress(&pdeg, g_deg);
    cudaMemsetAsync(pdeg, 0, N_NODES * sizeof(int), 0);

    k_pre      <<<DEG_BLK + 9, 256>>>(ei, W);
    k_scan     <<<SCAN_NB, 256>>>();
    k_linear   <<<LIN_BLK, 256>>>(x, ei);
    k_aggregate<<<(N_NODES / 2 * 32) / 256, 256>>>(b, out);   // 6250 blocks
}